// round 14
// baseline (speedup 1.0000x reference)
#include <cuda_runtime.h>
#include <cuda_fp16.h>
#include <cstdint>

// Problem constants
#define NN 50000
#define FF 64
#define HH 128

// ---------------- device scratch (static globals, no cudaMalloc) -------------
__device__ float g_deg[NN];
__device__ float g_dinv[NN];
__device__ float g_AX[(size_t)NN * FF];          // aggregated X  (N x 64) fp32
__device__ float g_Z[(size_t)NN * HH];           // Z gate fp32
__device__ uint4 g_AX16[(size_t)NN * 8];         // AX as fp16   (64 halves/row)
__device__ uint4 g_Hs16[(size_t)NN * 16];        // Hs as fp16   (128 halves/row)
__device__ uint4 g_HsR16[(size_t)NN * 16];       // Hs*R as fp16 (GEMM1 epilogue)
__device__ uint4 g_reluh16[(size_t)NN * 16];     // relu(h) fp16 (GEMM2 epilogue)
// pre-permuted fp16 weights (paired-column fragment order):
//  6 gate blocks of 6144 uint32 (64 cols x 192 k) + 1 Lout block of 4096 (64 x 128)
//  uint32 index within a block: ((ks*4 + cp)*32 + lane)*4 + ce*2 + jh
__device__ uint32_t g_Bp[6 * 6144 + 4096];
__device__ float g_bcat[384];                    // packed gate biases
// cross-phase flags (zeroed each replay in k_dinvax)
__device__ int g_flagC[400];   // cvt -> GEMM1   (target 4 per row-block)
__device__ int g_flag1[400];   // GEMM1 -> GEMM2 (target 4)
__device__ int g_flag2[400];   // GEMM2 -> GEMM3 (target 2)

// ---------------- helpers -----------------------------------------------------
__device__ __forceinline__ uint32_t f2h2(float lo, float hi) {
    __half2 h = __floats2half2_rn(lo, hi);
    return *(uint32_t*)&h;
}
__device__ __forceinline__ void mma_f16(float* c, const uint32_t* a, const uint32_t* b) {
    asm volatile(
        "mma.sync.aligned.m16n8k16.row.col.f32.f16.f16.f32 "
        "{%0,%1,%2,%3}, {%4,%5,%6,%7}, {%8,%9}, {%0,%1,%2,%3};"
        : "+f"(c[0]), "+f"(c[1]), "+f"(c[2]), "+f"(c[3])
        : "r"(a[0]), "r"(a[1]), "r"(a[2]), "r"(a[3]), "r"(b[0]), "r"(b[1]));
}
__device__ __forceinline__ void flag_arrive(int* flag) {
    __threadfence();
    __syncthreads();
    if (threadIdx.x == 0) atomicAdd(flag, 1);
}
__device__ __forceinline__ void flag_wait(int* flag, int target) {
    if (threadIdx.x == 0) {
        while (atomicAdd(flag, 0) < target) __nanosleep(64);
        __threadfence();
    }
    __syncthreads();
}

// ---------------- fused: weight pack + Hs->fp16 + degree ----------------------
#define PACKB 162   // ceil((6*6144 + 4096 + 384) / 256)
#define HSB   3125  // ceil(NN*16 / 256)

__global__ void k_packdeg(const float* Wz, const float* bz,
                          const float* Wr, const float* br,
                          const float* Wh, const float* bh,
                          const float* Lz, const float* Lzb,
                          const float* Lr, const float* Lrb,
                          const float* Lh, const float* Lhb,
                          const float* LoW, const float* Hs,
                          const int* __restrict__ ei,
                          const float* __restrict__ ew, int E) {
    if (blockIdx.x >= PACKB + HSB) {
        int e = (blockIdx.x - PACKB - HSB) * 256 + threadIdx.x;
        if (e < E) atomicAdd(&g_deg[ei[E + e]], ew[e]);
        return;
    }
    if (blockIdx.x >= PACKB) {
        int u = (blockIdx.x - PACKB) * 256 + threadIdx.x;
        if (u < NN * 16) {
            int row = u >> 4, q = u & 15;
            float4 a = *(const float4*)(Hs + (size_t)row * 128 + q * 8);
            float4 b = *(const float4*)(Hs + (size_t)row * 128 + q * 8 + 4);
            uint4 o;
            o.x = f2h2(a.x, a.y); o.y = f2h2(a.z, a.w);
            o.z = f2h2(b.x, b.y); o.w = f2h2(b.z, b.w);
            g_Hs16[(size_t)row * 16 + q] = o;
        }
        return;
    }
    int idx = blockIdx.x * blockDim.x + threadIdx.x;
    const int TG = 6 * 6144;
    const int TL = TG + 4096;
    if (idx < TG) {
        int blk = idx / 6144;
        int r   = idx % 6144;
        int jh   = r & 1;
        int ce   = (r >> 1) & 1;
        int lane = (r >> 2) & 31;
        int cp   = (r >> 7) & 3;
        int ks   = r >> 9;            // 0..11
        int n  = blk * 64 + (cp * 2 + ce) * 8 + (lane >> 2);
        int k0 = ks * 16 + jh * 8 + (lane & 3) * 2;
        int g = n >> 7;
        int jj = n & 127;
        const float* W = (g == 0) ? Wz : (g == 1) ? Wr : Wh;
        const float* L = (g == 0) ? Lz : (g == 1) ? Lr : Lh;
        float v[2];
        #pragma unroll
        for (int e = 0; e < 2; e++) {
            int k = k0 + e;
            if (k < 64) {
                float s = 0.f;
                #pragma unroll 8
                for (int t = 0; t < 128; t++) s += W[k * 128 + t] * L[t * 128 + jj];
                v[e] = s;
            } else {
                v[e] = L[(128 + (k - 64)) * 128 + jj];
            }
        }
        g_Bp[idx] = f2h2(v[0], v[1]);
    } else if (idx < TL) {
        int r = idx - TG;
        int jh   = r & 1;
        int ce   = (r >> 1) & 1;
        int lane = (r >> 2) & 31;
        int cp   = (r >> 7) & 3;
        int ks   = r >> 9;            // 0..7
        int n  = (cp * 2 + ce) * 8 + (lane >> 2);
        int k0 = ks * 16 + jh * 8 + (lane & 3) * 2;
        g_Bp[idx] = f2h2(LoW[k0 * 64 + n], LoW[(k0 + 1) * 64 + n]);
    } else if (idx < TL + 384) {
        int j = idx - TL;
        int g = j >> 7;
        int jj = j & 127;
        const float* bg = (g == 0) ? bz : (g == 1) ? br : bh;
        const float* L  = (g == 0) ? Lz : (g == 1) ? Lr : Lh;
        const float* Lb = (g == 0) ? Lzb : (g == 1) ? Lrb : Lhb;
        float v = Lb[jj];
        for (int t = 0; t < 128; t++) v += bg[t] * L[t * 128 + jj];
        g_bcat[j] = v;
    }
}

// fused: dinv = rsqrt(deg+1), reset deg, AX self-loop init; zero phase flags
__global__ void k_dinvax(const float* __restrict__ X) {
    if (blockIdx.x == 0) {
        for (int i = threadIdx.x; i < 400; i += 256) {
            g_flagC[i] = 0; g_flag1[i] = 0; g_flag2[i] = 0;
        }
    }
    int tid = blockIdx.x * blockDim.x + threadIdx.x;
    if (tid >= NN * 16) return;
    int i = tid >> 4, q = tid & 15;
    float d  = g_deg[i] + 1.0f;       // self-loop weight 1
    float di = rsqrtf(d);
    __syncwarp();
    if (q == 0) { g_dinv[i] = di; g_deg[i] = 0.f; }
    float s = di * di;
    float4 x = reinterpret_cast<const float4*>(X + (size_t)i * 64)[q];
    float4 v = make_float4(x.x * s, x.y * s, x.z * s, x.w * s);
    reinterpret_cast<float4*>(g_AX + (size_t)i * 64)[q] = v;
}

// Edge scatter: AX[dst] += dinv[src]*w*dinv[dst] * X[src]   (16 threads/edge)
__global__ void k_agg(const int* __restrict__ ei, const float* __restrict__ ew,
                      const float* __restrict__ X, int E) {
    int tid = blockIdx.x * blockDim.x + threadIdx.x;
    int e = tid >> 4;
    if (e >= E) return;
    int q = tid & 15;
    int s = ei[e];
    int d = ei[E + e];
    float norm = g_dinv[s] * ew[e] * g_dinv[d];
    float4 x = reinterpret_cast<const float4*>(X + (size_t)s * 64)[q];
    float* p = g_AX + (size_t)d * 64 + q * 4;
    asm volatile("red.global.add.v4.f32 [%0], {%1, %2, %3, %4};"
                 :: "l"(p), "f"(x.x * norm), "f"(x.y * norm),
                    "f"(x.z * norm), "f"(x.w * norm)
                 : "memory");
}

// ---------------- GEMM body (R13 champion, as device function) ----------------
#define STR2 20     // uint32 per A smem row (conflict-free fragment reads)

template <int NCH1, int NCH2, int MODE>
__device__ __forceinline__ void gemm_body(
    uint32_t* As2, uint32_t* Bs,
    int x, int ycb,
    const uint4* __restrict__ A1, int s1q,
    const uint4* __restrict__ A2, int s2q,
    const uint32_t* __restrict__ Bp,
    const float* __restrict__ bias,
    const float* __restrict__ Zbuf,
    const float* __restrict__ Hs,
    float* __restrict__ out0,
    uint4* __restrict__ out16) {
    constexpr int NCH = NCH1 + NCH2;
    constexpr int NKS = NCH * 2;

    const int t    = threadIdx.x;
    const int lane = t & 31;
    const int wid  = t >> 5;
    const int gid  = lane >> 2;
    const int tig  = lane & 3;
    const int warpRow = wid & 3;
    const int warpCol = wid >> 2;
    const int blockRow = x * 128;
    const int colGrp   = ycb * 64;

    // ---- whole-K B copy ----
    {
        const uint4* src = (const uint4*)(Bp + (size_t)ycb * (NKS * 512));
        uint4* dst = (uint4*)Bs;
        #pragma unroll
        for (int i = 0; i < (NKS * 128) / 256; i++) dst[t + i * 256] = src[t + i * 256];
    }

    float acc[2][4][4];
    #pragma unroll
    for (int mi = 0; mi < 2; mi++)
        #pragma unroll
        for (int ni = 0; ni < 4; ni++)
            #pragma unroll
            for (int c = 0; c < 4; c++) acc[mi][ni][c] = 0.f;

    for (int ch = 0; ch < NCH; ch++) {
        const uint4* src;
        int sq, cl;
        if (ch < NCH1) { src = A1; sq = s1q; cl = ch; }
        else           { src = A2; sq = s2q; cl = ch - NCH1; }
        #pragma unroll
        for (int it = 0; it < 2; it++) {
            int i = t + it * 256;
            int row = i >> 2;
            int q   = i & 3;
            int grow = blockRow + row;
            uint4 v = make_uint4(0u, 0u, 0u, 0u);
            if (grow < NN) v = src[(size_t)grow * sq + cl * 4 + q];
            *(uint4*)&As2[row * STR2 + q * 4] = v;
        }
        __syncthreads();

        #pragma unroll
        for (int s = 0; s < 2; s++) {
            const int ksg = ch * 2 + s;
            uint32_t a[2][4];
            #pragma unroll
            for (int mi = 0; mi < 2; mi++) {
                int r0 = warpRow * 32 + mi * 16 + gid;
                a[mi][0] = As2[r0 * STR2 + s * 8 + tig];
                a[mi][1] = As2[(r0 + 8) * STR2 + s * 8 + tig];
                a[mi][2] = As2[r0 * STR2 + s * 8 + tig + 4];
                a[mi][3] = As2[(r0 + 8) * STR2 + s * 8 + tig + 4];
            }
            uint32_t b[4][2];
            #pragma unroll
            for (int np = 0; np < 2; np++) {
                int cp = warpCol * 2 + np;
                uint4 bv = *(const uint4*)&Bs[((ksg * 4 + cp) * 32 + lane) * 4];
                b[np * 2][0]     = bv.x; b[np * 2][1]     = bv.y;
                b[np * 2 + 1][0] = bv.z; b[np * 2 + 1][1] = bv.w;
            }
            #pragma unroll
            for (int mi = 0; mi < 2; mi++)
                #pragma unroll
                for (int ni = 0; ni < 4; ni++)
                    mma_f16(acc[mi][ni], a[mi], b[ni]);
        }
        __syncthreads();
    }

    // ---- epilogue ----
    #pragma unroll
    for (int mi = 0; mi < 2; mi++) {
        #pragma unroll
        for (int half = 0; half < 2; half++) {
            int row = blockRow + warpRow * 32 + mi * 16 + gid + half * 8;
            if (row >= NN) continue;
            #pragma unroll
            for (int ni = 0; ni < 4; ni++) {
                int col  = warpCol * 32 + ni * 8 + tig * 2;
                int gcol = colGrp + col;
                float v0 = acc[mi][ni][half * 2]     + bias[gcol];
                float v1 = acc[mi][ni][half * 2 + 1] + bias[gcol + 1];
                if (MODE == 0) {
                    float s0 = 1.f / (1.f + expf(-v0));
                    float s1 = 1.f / (1.f + expf(-v1));
                    if (ycb < 2) {
                        *(float2*)(out0 + (size_t)row * 128 + gcol) = make_float2(s0, s1);
                    } else {
                        int rcol = gcol - 128;
                        float2 hs = *(const float2*)(Hs + (size_t)row * 128 + rcol);
                        ((uint32_t*)out16)[(size_t)row * 64 + (rcol >> 1)] =
                            f2h2(hs.x * s0, hs.y * s1);
                    }
                } else if (MODE == 1) {
                    float2 z  = *(const float2*)(Zbuf + (size_t)row * 128 + gcol);
                    float2 hs = *(const float2*)(Hs + (size_t)row * 128 + gcol);
                    float h0 = z.x * hs.x + (1.f - z.x) * tanhf(v0);
                    float h1 = z.y * hs.y + (1.f - z.y) * tanhf(v1);
                    *(float2*)(out0 + (size_t)row * 128 + gcol) = make_float2(h0, h1);
                    ((uint32_t*)out16)[(size_t)row * 64 + (gcol >> 1)] =
                        f2h2(fmaxf(h0, 0.f), fmaxf(h1, 0.f));
                } else {
                    *(float2*)(out0 + (size_t)row * 64 + gcol) = make_float2(v0, v1);
                }
            }
        }
    }
}

// ---------------- mega kernel: cvt + GEMM1 + GEMM2 + GEMM3 in one launch ------
// bid [0,1564):      AX fp32 -> fp16 (32 rows/block), arrive flagC[bid>>2]
// bid [1564,3128):   GEMM1 (x = u>>2, y = u&3), wait flagC[x]==4, arrive flag1[x]
// bid [3128,3910):   GEMM2 (x = u>>1, cb = u&1), wait flag1[x]==4, arrive flag2[x]
// bid [3910,4301):   GEMM3 (x = u),   wait flag2[x]==2
__global__ void __launch_bounds__(256)
k_mega(const float* __restrict__ Hs,
       const float* __restrict__ LoB,
       float* __restrict__ out_h,
       float* __restrict__ out_y) {
    extern __shared__ uint32_t sm[];
    uint32_t* As2 = sm;            // 2560
    uint32_t* Bs  = sm + 2560;     // up to 6144

    const int bid = blockIdx.x;
    if (bid < 1564) {
        // ---- AX fp32 -> fp16 ----
        int u = bid * 256 + threadIdx.x;
        if (u < NN * 8) {
            int row = u >> 3, q = u & 7;
            float4 a = *(const float4*)(g_AX + (size_t)row * 64 + q * 8);
            float4 b = *(const float4*)(g_AX + (size_t)row * 64 + q * 8 + 4);
            uint4 o;
            o.x = f2h2(a.x, a.y); o.y = f2h2(a.z, a.w);
            o.z = f2h2(b.x, b.y); o.w = f2h2(b.z, b.w);
            g_AX16[(size_t)row * 8 + q] = o;
        }
        flag_arrive(&g_flagC[bid >> 2]);
    } else if (bid < 3128) {
        int u = bid - 1564;
        int x = u >> 2, y = u & 3;
        flag_wait(&g_flagC[x], 4);
        gemm_body<2, 4, 0>(As2, Bs, x, y,
                           g_AX16, 8, g_Hs16, 16,
                           g_Bp, g_bcat, nullptr, Hs, g_Z, g_HsR16);
        flag_arrive(&g_flag1[x]);
    } else if (bid < 3910) {
        int u = bid - 3128;
        int x = u >> 1, cb = u & 1;
        flag_wait(&g_flag1[x], 4);
        gemm_body<2, 4, 1>(As2, Bs, x, cb,
                           g_AX16, 8, g_HsR16, 16,
                           g_Bp + 4 * 6144, g_bcat + 256, g_Z, Hs, out_h, g_reluh16);
        flag_arrive(&g_flag2[x]);
    } else {
        int x = bid - 3910;
        flag_wait(&g_flag2[x], 2);
        gemm_body<4, 0, 2>(As2, Bs, x, 0,
                           g_reluh16, 16, nullptr, 16,
                           g_Bp + 6 * 6144, LoB, nullptr, nullptr, out_y, nullptr);
    }
}

// ---------------- launch ------------------------------------------------------
extern "C" void kernel_launch(void* const* d_in, const int* in_sizes, int n_in,
                              void* d_out, int out_size) {
    const int*   ei  = (const int*)d_in[0];
    const float* X   = (const float*)d_in[1];
    const float* ew  = (const float*)d_in[2];
    const float* Hs  = (const float*)d_in[3];
    const float* Wz  = (const float*)d_in[4];
    const float* bz  = (const float*)d_in[5];
    const float* Wr  = (const float*)d_in[6];
    const float* br  = (const float*)d_in[7];
    const float* Wh  = (const float*)d_in[8];
    const float* bh  = (const float*)d_in[9];
    const float* Lz  = (const float*)d_in[10];
    const float* Lzb = (const float*)d_in[11];
    const float* Lr  = (const float*)d_in[12];
    const float* Lrb = (const float*)d_in[13];
    const float* Lh  = (const float*)d_in[14];
    const float* Lhb = (const float*)d_in[15];
    const float* LoW = (const float*)d_in[16];
    const float* LoB = (const float*)d_in[17];

    const int E = in_sizes[2];

    float* out   = (float*)d_out;
    float* out_y = out;                       // N x 64
    float* out_h = out + (size_t)NN * FF;     // N x 128

    const int smMega = (2560 + 6144) * 4;     // 34816 bytes (< 48KB default)

    // 1. fused: weight pack + Hs->fp16 + degree scatter
    k_packdeg<<<PACKB + HSB + (E + 255) / 256, 256>>>(
        Wz, bz, Wr, br, Wh, bh, Lz, Lzb, Lr, Lrb, Lh, Lhb, LoW, Hs, ei, ew, E);
    // 2. dinv + AX self-loop init (+ deg reset) + flag zeroing
    k_dinvax<<<(NN * 16 + 255) / 256, 256>>>(X);
    // 3. aggregate X once (GCN linearity)
    k_agg<<<(E * 16 + 255) / 256, 256>>>(ei, ew, X, E);
    // 4. mega: cvt + GEMM1 + GEMM2 + GEMM3 (row-local flag chaining)
    k_mega<<<4301, 256, smMega>>>(Hs, LoB, out_h, out_y);
}

// round 15
// speedup vs baseline: 1.1941x; 1.1941x over previous
#include <cuda_runtime.h>
#include <cuda_fp16.h>
#include <cstdint>

// Problem constants
#define NN 50000
#define FF 64
#define HH 128

// ---------------- device scratch (static globals, no cudaMalloc) -------------
__device__ float g_deg[NN];
__device__ float g_dinv[NN];
__device__ float g_Z[(size_t)NN * HH];           // Z gate fp32
__device__ uint4 g_X16[(size_t)NN * 8];          // X as fp16    (64 halves/row)
__device__ uint4 g_AX16[(size_t)NN * 8];         // AX fp16 (accumulated in fp16!)
__device__ uint4 g_Hs16[(size_t)NN * 16];        // Hs as fp16   (128 halves/row)
__device__ uint4 g_HsR16[(size_t)NN * 16];       // Hs*R as fp16 (GEMM1 epilogue)
__device__ uint4 g_reluh16[(size_t)NN * 16];     // relu(h) fp16 (GEMM2 epilogue)
// pre-permuted fp16 weights (paired-column fragment order):
//  6 gate blocks of 6144 uint32 (64 cols x 192 k) + 1 Lout block of 4096 (64 x 128)
//  uint32 index within a block: ((ks*4 + cp)*32 + lane)*4 + ce*2 + jh
__device__ uint32_t g_Bp[6 * 6144 + 4096];
__device__ float g_bcat[384];                    // packed gate biases

// ---------------- helpers -----------------------------------------------------
__device__ __forceinline__ uint32_t f2h2(float lo, float hi) {
    __half2 h = __floats2half2_rn(lo, hi);
    return *(uint32_t*)&h;
}
__device__ __forceinline__ void mma_f16(float* c, const uint32_t* a, const uint32_t* b) {
    asm volatile(
        "mma.sync.aligned.m16n8k16.row.col.f32.f16.f16.f32 "
        "{%0,%1,%2,%3}, {%4,%5,%6,%7}, {%8,%9}, {%0,%1,%2,%3};"
        : "+f"(c[0]), "+f"(c[1]), "+f"(c[2]), "+f"(c[3])
        : "r"(a[0]), "r"(a[1]), "r"(a[2]), "r"(a[3]), "r"(b[0]), "r"(b[1]));
}

// ---------------- fused: weight pack + X->fp16 + degree -----------------------
#define PACKB 162   // ceil((6*6144 + 4096 + 384) / 256)
#define XB    1563  // ceil(NN*8 / 256)

__global__ void k_packdeg(const float* Wz, const float* bz,
                          const float* Wr, const float* br,
                          const float* Wh, const float* bh,
                          const float* Lz, const float* Lzb,
                          const float* Lr, const float* Lrb,
                          const float* Lh, const float* Lhb,
                          const float* LoW, const float* X,
                          const int* __restrict__ ei,
                          const float* __restrict__ ew, int E) {
    if (blockIdx.x >= PACKB + XB) {
        int e = (blockIdx.x - PACKB - XB) * 256 + threadIdx.x;
        if (e < E) atomicAdd(&g_deg[ei[E + e]], ew[e]);
        return;
    }
    if (blockIdx.x >= PACKB) {
        int u = (blockIdx.x - PACKB) * 256 + threadIdx.x;
        if (u < NN * 8) {
            int row = u >> 3, q = u & 7;
            float4 a = *(const float4*)(X + (size_t)row * 64 + q * 8);
            float4 b = *(const float4*)(X + (size_t)row * 64 + q * 8 + 4);
            uint4 o;
            o.x = f2h2(a.x, a.y); o.y = f2h2(a.z, a.w);
            o.z = f2h2(b.x, b.y); o.w = f2h2(b.z, b.w);
            g_X16[(size_t)row * 8 + q] = o;
        }
        return;
    }
    int idx = blockIdx.x * blockDim.x + threadIdx.x;
    const int TG = 6 * 6144;
    const int TL = TG + 4096;
    if (idx < TG) {
        int blk = idx / 6144;
        int r   = idx % 6144;
        // paired-column layout decomposition
        int jh   = r & 1;
        int ce   = (r >> 1) & 1;
        int lane = (r >> 2) & 31;
        int cp   = (r >> 7) & 3;
        int ks   = r >> 9;            // 0..11
        int n  = blk * 64 + (cp * 2 + ce) * 8 + (lane >> 2);
        int k0 = ks * 16 + jh * 8 + (lane & 3) * 2;
        int g = n >> 7;
        int jj = n & 127;
        const float* W = (g == 0) ? Wz : (g == 1) ? Wr : Wh;
        const float* L = (g == 0) ? Lz : (g == 1) ? Lr : Lh;
        float v[2];
        #pragma unroll
        for (int e = 0; e < 2; e++) {
            int k = k0 + e;
            if (k < 64) {
                float s = 0.f;
                #pragma unroll 8
                for (int t = 0; t < 128; t++) s += W[k * 128 + t] * L[t * 128 + jj];
                v[e] = s;
            } else {
                v[e] = L[(128 + (k - 64)) * 128 + jj];
            }
        }
        g_Bp[idx] = f2h2(v[0], v[1]);
    } else if (idx < TL) {
        int r = idx - TG;
        int jh   = r & 1;
        int ce   = (r >> 1) & 1;
        int lane = (r >> 2) & 31;
        int cp   = (r >> 7) & 3;
        int ks   = r >> 9;            // 0..7
        int n  = (cp * 2 + ce) * 8 + (lane >> 2);
        int k0 = ks * 16 + jh * 8 + (lane & 3) * 2;
        g_Bp[idx] = f2h2(LoW[k0 * 64 + n], LoW[(k0 + 1) * 64 + n]);
    } else if (idx < TL + 384) {
        int j = idx - TL;
        int g = j >> 7;
        int jj = j & 127;
        const float* bg = (g == 0) ? bz : (g == 1) ? br : bh;
        const float* L  = (g == 0) ? Lz : (g == 1) ? Lr : Lh;
        const float* Lb = (g == 0) ? Lzb : (g == 1) ? Lrb : Lhb;
        float v = Lb[jj];
        for (int t = 0; t < 128; t++) v += bg[t] * L[t * 128 + jj];
        g_bcat[j] = v;
    }
}

// fused: dinv = rsqrt(deg+1), reset deg, AX16 self-loop init (fp16);
// Hs->fp16 for the upper tid range
__global__ void k_dinvax(const float* __restrict__ X, const float* __restrict__ Hs) {
    int tid = blockIdx.x * blockDim.x + threadIdx.x;
    if (tid < NN * 8) {
        int i = tid >> 3, q = tid & 7;
        float d  = g_deg[i] + 1.0f;       // self-loop weight 1
        float di = rsqrtf(d);
        __syncwarp();
        if (q == 0) { g_dinv[i] = di; g_deg[i] = 0.f; }
        float s = di * di;
        float4 a = *(const float4*)(X + (size_t)i * 64 + q * 8);
        float4 b = *(const float4*)(X + (size_t)i * 64 + q * 8 + 4);
        uint4 o;
        o.x = f2h2(a.x * s, a.y * s); o.y = f2h2(a.z * s, a.w * s);
        o.z = f2h2(b.x * s, b.y * s); o.w = f2h2(b.z * s, b.w * s);
        g_AX16[(size_t)i * 8 + q] = o;
    } else if (tid < NN * 8 + NN * 16) {
        int u = tid - NN * 8;
        int row = u >> 4, q = u & 15;
        float4 a = *(const float4*)(Hs + (size_t)row * 128 + q * 8);
        float4 b = *(const float4*)(Hs + (size_t)row * 128 + q * 8 + 4);
        uint4 o;
        o.x = f2h2(a.x, a.y); o.y = f2h2(a.z, a.w);
        o.z = f2h2(b.x, b.y); o.w = f2h2(b.z, b.w);
        g_Hs16[(size_t)row * 16 + q] = o;
    }
}

// Edge scatter (fp16): AX16[dst] += fp16(norm * X16[src])   (8 threads/edge)
__global__ void k_agg(const int* __restrict__ ei, const float* __restrict__ ew, int E) {
    int tid = blockIdx.x * blockDim.x + threadIdx.x;
    int e = tid >> 3;
    if (e >= E) return;
    int q = tid & 7;
    int s = ei[e];
    int d = ei[E + e];
    float norm = g_dinv[s] * ew[e] * g_dinv[d];
    uint4 x = g_X16[(size_t)s * 8 + q];
    float2 f0 = __half22float2(*(__half2*)&x.x);
    float2 f1 = __half22float2(*(__half2*)&x.y);
    float2 f2 = __half22float2(*(__half2*)&x.z);
    float2 f3 = __half22float2(*(__half2*)&x.w);
    uint32_t h0 = f2h2(f0.x * norm, f0.y * norm);
    uint32_t h1 = f2h2(f1.x * norm, f1.y * norm);
    uint32_t h2 = f2h2(f2.x * norm, f2.y * norm);
    uint32_t h3 = f2h2(f3.x * norm, f3.y * norm);
    uint32_t* p = (uint32_t*)&g_AX16[(size_t)d * 8 + q];
    asm volatile("red.global.add.noftz.v4.f16x2 [%0], {%1, %2, %3, %4};"
                 :: "l"(p), "r"(h0), "r"(h1), "r"(h2), "r"(h3) : "memory");
}

// ---------------- fp16 tensor-core GEMM (R13 champion, unchanged) -------------
// Block tile 128 x 64, 8 warps, warp tile 32x32, BK=32. A fill = pure uint4 copy.
// B fragments: paired-column layout -> 2 x LDS.128 per k16-step.
// MODE 0 (GEMM1): sigmoid; blockIdx.y<2 -> Z fp32 (stride 128);
//                 blockIdx.y>=2 -> HsR16 = fp16(Hs * R)
// MODE 1 (GEMM2): tanh + GRU -> h fp32 (stride 128) + reluh16
// MODE 2 (GEMM3): plain -> y fp32 (stride 64)
#define STR2 20     // uint32 per A smem row (conflict-free fragment reads)

template <int NCH1, int NCH2, int MODE>
__global__ void __launch_bounds__(256)
gemm16(const uint4* __restrict__ A1, int s1q,    // uint4 stride per row
       const uint4* __restrict__ A2, int s2q,
       const uint32_t* __restrict__ Bp,
       const float* __restrict__ bias,
       const float* __restrict__ Zbuf,           // MODE1: Z fp32 (stride 128)
       const float* __restrict__ Hs,             // MODE0 R-half / MODE1: Hs fp32
       float* __restrict__ out0,
       uint4* __restrict__ out16) {
    constexpr int NCH = NCH1 + NCH2;             // 32-k chunks
    constexpr int NKS = NCH * 2;                 // k16 steps
    __shared__ uint32_t As2[128 * STR2];
    __shared__ uint32_t Bs[NKS * 512];

    const int t    = threadIdx.x;
    const int lane = t & 31;
    const int wid  = t >> 5;
    const int gid  = lane >> 2;
    const int tig  = lane & 3;
    const int warpRow = wid & 3;
    const int warpCol = wid >> 2;
    const int blockRow = blockIdx.x * 128;
    const int colGrp   = blockIdx.y * 64;

    // ---- whole-K B copy ----
    {
        const uint4* src = (const uint4*)(Bp + (size_t)blockIdx.y * (NKS * 512));
        uint4* dst = (uint4*)Bs;
        #pragma unroll
        for (int i = 0; i < (NKS * 128) / 256; i++) dst[t + i * 256] = src[t + i * 256];
    }

    float acc[2][4][4];
    #pragma unroll
    for (int mi = 0; mi < 2; mi++)
        #pragma unroll
        for (int ni = 0; ni < 4; ni++)
            #pragma unroll
            for (int c = 0; c < 4; c++) acc[mi][ni][c] = 0.f;

    for (int ch = 0; ch < NCH; ch++) {
        // ---- A tile fill: 2 x (LDG.128 -> STS.128) per thread, no ALU ----
        const uint4* src;
        int sq, cl;
        if (ch < NCH1) { src = A1; sq = s1q; cl = ch; }
        else           { src = A2; sq = s2q; cl = ch - NCH1; }
        #pragma unroll
        for (int it = 0; it < 2; it++) {
            int i = t + it * 256;
            int row = i >> 2;
            int q   = i & 3;
            int grow = blockRow + row;
            uint4 v = make_uint4(0u, 0u, 0u, 0u);
            if (grow < NN) v = src[(size_t)grow * sq + cl * 4 + q];
            *(uint4*)&As2[row * STR2 + q * 4] = v;
        }
        __syncthreads();

        // ---- 2 k16-steps: per step 8 A-LDS.32 + 2 B-LDS.128 + 8 MMA ----
        #pragma unroll
        for (int s = 0; s < 2; s++) {
            const int ksg = ch * 2 + s;
            uint32_t a[2][4];
            #pragma unroll
            for (int mi = 0; mi < 2; mi++) {
                int r0 = warpRow * 32 + mi * 16 + gid;
                a[mi][0] = As2[r0 * STR2 + s * 8 + tig];
                a[mi][1] = As2[(r0 + 8) * STR2 + s * 8 + tig];
                a[mi][2] = As2[r0 * STR2 + s * 8 + tig + 4];
                a[mi][3] = As2[(r0 + 8) * STR2 + s * 8 + tig + 4];
            }
            uint32_t b[4][2];
            #pragma unroll
            for (int np = 0; np < 2; np++) {
                int cp = warpCol * 2 + np;
                uint4 bv = *(const uint4*)&Bs[((ksg * 4 + cp) * 32 + lane) * 4];
                b[np * 2][0]     = bv.x; b[np * 2][1]     = bv.y;
                b[np * 2 + 1][0] = bv.z; b[np * 2 + 1][1] = bv.w;
            }
            #pragma unroll
            for (int mi = 0; mi < 2; mi++)
                #pragma unroll
                for (int ni = 0; ni < 4; ni++)
                    mma_f16(acc[mi][ni], a[mi], b[ni]);
        }
        __syncthreads();
    }

    // ---- epilogue ----
    #pragma unroll
    for (int mi = 0; mi < 2; mi++) {
        #pragma unroll
        for (int half = 0; half < 2; half++) {
            int row = blockRow + warpRow * 32 + mi * 16 + gid + half * 8;
            if (row >= NN) continue;
            #pragma unroll
            for (int ni = 0; ni < 4; ni++) {
                int col  = warpCol * 32 + ni * 8 + tig * 2;
                int gcol = colGrp + col;
                float v0 = acc[mi][ni][half * 2]     + bias[gcol];
                float v1 = acc[mi][ni][half * 2 + 1] + bias[gcol + 1];
                if (MODE == 0) {
                    float s0 = 1.f / (1.f + expf(-v0));
                    float s1 = 1.f / (1.f + expf(-v1));
                    if (blockIdx.y < 2) {
                        *(float2*)(out0 + (size_t)row * 128 + gcol) = make_float2(s0, s1);
                    } else {
                        int rcol = gcol - 128;
                        float2 hs = *(const float2*)(Hs + (size_t)row * 128 + rcol);
                        ((uint32_t*)out16)[(size_t)row * 64 + (rcol >> 1)] =
                            f2h2(hs.x * s0, hs.y * s1);
                    }
                } else if (MODE == 1) {
                    float2 z  = *(const float2*)(Zbuf + (size_t)row * 128 + gcol);
                    float2 hs = *(const float2*)(Hs + (size_t)row * 128 + gcol);
                    float h0 = z.x * hs.x + (1.f - z.x) * tanhf(v0);
                    float h1 = z.y * hs.y + (1.f - z.y) * tanhf(v1);
                    *(float2*)(out0 + (size_t)row * 128 + gcol) = make_float2(h0, h1);
                    ((uint32_t*)out16)[(size_t)row * 64 + (gcol >> 1)] =
                        f2h2(fmaxf(h0, 0.f), fmaxf(h1, 0.f));
                } else {
                    *(float2*)(out0 + (size_t)row * 64 + gcol) = make_float2(v0, v1);
                }
            }
        }
    }
}

// ---------------- launch ------------------------------------------------------
extern "C" void kernel_launch(void* const* d_in, const int* in_sizes, int n_in,
                              void* d_out, int out_size) {
    const int*   ei  = (const int*)d_in[0];
    const float* X   = (const float*)d_in[1];
    const float* ew  = (const float*)d_in[2];
    const float* Hs  = (const float*)d_in[3];
    const float* Wz  = (const float*)d_in[4];
    const float* bz  = (const float*)d_in[5];
    const float* Wr  = (const float*)d_in[6];
    const float* br  = (const float*)d_in[7];
    const float* Wh  = (const float*)d_in[8];
    const float* bh  = (const float*)d_in[9];
    const float* Lz  = (const float*)d_in[10];
    const float* Lzb = (const float*)d_in[11];
    const float* Lr  = (const float*)d_in[12];
    const float* Lrb = (const float*)d_in[13];
    const float* Lh  = (const float*)d_in[14];
    const float* Lhb = (const float*)d_in[15];
    const float* LoW = (const float*)d_in[16];
    const float* LoB = (const float*)d_in[17];

    const int E = in_sizes[2];

    float* out   = (float*)d_out;
    float* out_y = out;                       // N x 64
    float* out_h = out + (size_t)NN * FF;     // N x 128

    void *pAX16, *pHs16, *pHsR16, *pReluh16, *pZ, *pBp, *pBcat;
    cudaGetSymbolAddress(&pAX16, g_AX16);
    cudaGetSymbolAddress(&pHs16, g_Hs16);
    cudaGetSymbolAddress(&pHsR16, g_HsR16);
    cudaGetSymbolAddress(&pReluh16, g_reluh16);
    cudaGetSymbolAddress(&pZ, g_Z);
    cudaGetSymbolAddress(&pBp, g_Bp);
    cudaGetSymbolAddress(&pBcat, g_bcat);

    // 1. fused: weight pack + X->fp16 + degree scatter
    k_packdeg<<<PACKB + XB + (E + 255) / 256, 256>>>(
        Wz, bz, Wr, br, Wh, bh, Lz, Lzb, Lr, Lrb, Lh, Lhb, LoW, X, ei, ew, E);
    // 2. dinv + AX16 self-loop init (fp16) + deg reset + Hs->fp16
    k_dinvax<<<(NN * 8 + NN * 16 + 255) / 256, 256>>>(X, Hs);
    // 3. aggregate X once (GCN linearity), fp16 gather + fp16 RMW
    k_agg<<<(E * 8 + 255) / 256, 256>>>(ei, ew, E);

    const int gridM = (NN + 127) / 128;  // 391

    // 4. GEMM1: [AX16 | Hs16] @ W1 -> sigmoid -> Z (fp32) + HsR16
    gemm16<2, 4, 0><<<dim3(gridM, 4), 256>>>(
        (const uint4*)pAX16, 8, (const uint4*)pHs16, 16,
        (const uint32_t*)pBp, (const float*)pBcat,
        nullptr, Hs, (float*)pZ, (uint4*)pHsR16);
    // 5. GEMM2: [AX16 | HsR16] @ W2 -> tanh -> GRU -> h + reluh16
    gemm16<2, 4, 1><<<dim3(gridM, 2), 256>>>(
        (const uint4*)pAX16, 8, (const uint4*)pHsR16, 16,
        (const uint32_t*)pBp + 4 * 6144, (const float*)pBcat + 256,
        (const float*)pZ, Hs, out_h, (uint4*)pReluh16);
    // 6. GEMM3: reluh16 @ Lout + b -> y
    gemm16<4, 0, 2><<<dim3(gridM, 1), 256>>>(
        (const uint4*)pReluh16, 16, nullptr, 16,
        (const uint32_t*)pBp + 6 * 6144, LoB,
        nullptr, nullptr, out_y, nullptr);
}